// round 4
// baseline (speedup 1.0000x reference)
#include <cuda_runtime.h>
#include <cuda_fp16.h>
#include <math.h>
#include <stdint.h>

#define Bb 2
#define Tt 2048
#define Ee 1024
#define Hh 16
#define Dd 64
#define BH 32
#define BT 4096  // B*T

static const size_t OUT_OFF = (size_t)Bb * Tt * Ee;  // 4194304 floats (out), then weights

// ---------------- scratch (device globals; no allocation allowed) ----------------
__device__ float g_q[BT * Ee];
__device__ float g_k[BT * Ee];
__device__ float g_v[BT * Ee];
__device__ float g_qr[BH * Tt * Dd];          // [bh, t, d]
__device__ float g_kr[BH * Tt * Dd];          // [bh, t, d]
__device__ float g_vt[BH * Dd * Tt];          // [bh, d, t]  (transposed for NT PV gemm)
__device__ float g_scores[(size_t)BH * Tt * Tt];  // 512MB: scores -> probs (fp16-quantized)
__device__ float g_attn[BT * Ee];             // [b, t, h*64+d]

// ---------------- generic batched NT GEMM: C = A (MxK) * B^T (B is NxK) + bias ----------------
template <int BM, int BN, int BK, int TM, int TN>
__global__ void __launch_bounds__((BM / TM) * (BN / TN))
gemm_nt(const float* __restrict__ A, const float* __restrict__ Bm,
        const float* __restrict__ bias, float* __restrict__ C,
        int M, int N, int K, int lda, int ldb, int ldc,
        long long sAz, long long sBz, long long sCz1, long long sCz2, int zdiv)
{
    constexpr int NT = (BM / TM) * (BN / TN);
    int z = blockIdx.z;
    A  += (long long)z * sAz;
    Bm += (long long)z * sBz;
    C  += (long long)(z / zdiv) * sCz1 + (long long)(z % zdiv) * sCz2;

    __shared__ float As[BK][BM];
    __shared__ float Bs[BK][BN];

    int tid = threadIdx.x;
    int tx = tid % (BN / TN);
    int ty = tid / (BN / TN);
    int row0 = blockIdx.y * BM;
    int col0 = blockIdx.x * BN;

    float acc[TM][TN];
#pragma unroll
    for (int i = 0; i < TM; i++)
#pragma unroll
        for (int j = 0; j < TN; j++) acc[i][j] = 0.0f;

    for (int k0 = 0; k0 < K; k0 += BK) {
#pragma unroll
        for (int off = tid * 4; off < BM * BK; off += NT * 4) {
            int r = off / BK, c = off % BK;
            float4 va = *(const float4*)&A[(size_t)(row0 + r) * lda + k0 + c];
            As[c + 0][r] = va.x; As[c + 1][r] = va.y;
            As[c + 2][r] = va.z; As[c + 3][r] = va.w;
        }
#pragma unroll
        for (int off = tid * 4; off < BN * BK; off += NT * 4) {
            int r = off / BK, c = off % BK;
            float4 vb = *(const float4*)&Bm[(size_t)(col0 + r) * ldb + k0 + c];
            Bs[c + 0][r] = vb.x; Bs[c + 1][r] = vb.y;
            Bs[c + 2][r] = vb.z; Bs[c + 3][r] = vb.w;
        }
        __syncthreads();
#pragma unroll
        for (int kk = 0; kk < BK; kk++) {
            float a[TM], b[TN];
#pragma unroll
            for (int i = 0; i < TM; i++) a[i] = As[kk][ty * TM + i];
#pragma unroll
            for (int j = 0; j < TN; j++) b[j] = Bs[kk][tx * TN + j];
#pragma unroll
            for (int i = 0; i < TM; i++)
#pragma unroll
                for (int j = 0; j < TN; j++) acc[i][j] = fmaf(a[i], b[j], acc[i][j]);
        }
        __syncthreads();
    }

#pragma unroll
    for (int i = 0; i < TM; i++) {
        int gr = row0 + ty * TM + i;
#pragma unroll
        for (int j = 0; j < TN; j++) {
            int gc = col0 + tx * TN + j;
            float cv = acc[i][j];
            if (bias) cv += bias[gc];
            C[(size_t)gr * ldc + gc] = cv;
        }
    }
}

// ---------------- prune (top-512 of 1024 per row) + head split + xPos ----------------
// mode 0: v  -> g_vt [bh, d, t]
// mode 1: q  -> scale 0.125, xPos (upscale)   -> [bh, t, d]
// mode 2: k  -> xPos (downscale)              -> [bh, t, d]
__global__ void __launch_bounds__(1024)
prune_transform(const float* __restrict__ X, float* __restrict__ out, int mode)
{
    int row = blockIdx.x;            // b*T + t
    int b = row >> 11;
    int t = row & 2047;
    int e = threadIdx.x;

    __shared__ float s[1024];
    __shared__ float vals[1024];

    float x = X[(size_t)row * 1024 + e];
    s[e] = x;
    __syncthreads();

    // bitonic ascending sort of a copy
    for (int k = 2; k <= 1024; k <<= 1) {
        for (int j = k >> 1; j > 0; j >>= 1) {
            int ixj = e ^ j;
            if (ixj > e) {
                float a = s[e], c = s[ixj];
                bool up = ((e & k) == 0);
                if ((a > c) == up) { s[e] = c; s[ixj] = a; }
            }
            __syncthreads();
        }
    }
    float thr = s[512];              // 512th largest value
    float m = (x >= thr) ? x : 0.0f;

    int h = e >> 6, d = e & 63;
    if (mode == 0) {
        out[((size_t)(b * 16 + h) * 64 + d) * 2048 + t] = m;
        return;
    }
    if (mode == 1) m *= 0.125f;      // D^-0.5
    vals[e] = m;
    __syncthreads();

    int i = d >> 1;
    float base = (2.0f * (float)i + 25.6f) / 89.6f;     // (2i + 0.4*Dh)/(1.4*Dh)
    float p = ((float)t - 1024.0f) / 512.0f;            // (t + min_pos)/SCALE_BASE
    if (mode == 2) p = -p;                              // downscale
    float sc = powf(base, p);
    float freq = powf(10000.0f, -(float)i / 32.0f);
    float ang = (float)t * freq;
    float sn = sinf(ang) * sc;
    float cs = cosf(ang) * sc;
    float partner = vals[e ^ 1];
    float o = (d & 1) ? (m * cs + partner * sn) : (m * cs - partner * sn);
    out[((size_t)(b * 16 + h) * 2048 + t) * 64 + d] = o;
}

// ---------------- row softmax + fp16 quantize; writes probs (in place) and d_out weights ----------------
__global__ void __launch_bounds__(256)
softmax_rows(float* __restrict__ scores, float* __restrict__ wout)
{
    int t = blockIdx.x;
    int bh = blockIdx.y;
    float* row = scores + ((size_t)bh * 2048 + t) * 2048;
    int tid = threadIdx.x;

    float v[8];
    float mx = -INFINITY;
#pragma unroll
    for (int i = 0; i < 8; i++) {
        v[i] = row[tid + i * 256];
        mx = fmaxf(mx, v[i]);
    }
    __shared__ float red[256];
    red[tid] = mx; __syncthreads();
    for (int s2 = 128; s2 > 0; s2 >>= 1) {
        if (tid < s2) red[tid] = fmaxf(red[tid], red[tid + s2]);
        __syncthreads();
    }
    mx = red[0];
    __syncthreads();

    float sm = 0.0f;
#pragma unroll
    for (int i = 0; i < 8; i++) { v[i] = expf(v[i] - mx); sm += v[i]; }
    red[tid] = sm; __syncthreads();
    for (int s2 = 128; s2 > 0; s2 >>= 1) {
        if (tid < s2) red[tid] += red[tid + s2];
        __syncthreads();
    }
    float inv = 1.0f / red[0];

    int b = bh >> 4, h = bh & 15;
    float* wrow = wout + ((size_t)(h * 2 + b) * 2048 + t) * 2048;
#pragma unroll
    for (int i = 0; i < 8; i++) {
        __half hh = __float2half(v[i] * inv);   // fp32 -> fp16 RN, matching .astype(float16)
        float f = __half2float(hh);
        row[tid + i * 256] = f;                 // probs for PV gemm
        wrow[tid + i * 256] = f;                // attn_weights output (upcast to fp32)
    }
}

extern "C" void kernel_launch(void* const* d_in, const int* in_sizes, int n_in,
                              void* d_out, int out_size)
{
    const float* query = (const float*)d_in[0];
    const float* key   = (const float*)d_in[1];
    const float* value = (const float*)d_in[2];
    const float* Wq = (const float*)d_in[3];
    const float* bq = (const float*)d_in[4];
    const float* Wk = (const float*)d_in[5];
    const float* bk = (const float*)d_in[6];
    const float* Wv = (const float*)d_in[7];
    const float* bv = (const float*)d_in[8];
    const float* Wo = (const float*)d_in[9];
    const float* bo = (const float*)d_in[10];
    float* out = (float*)d_out;

    float *qp, *kp, *vp, *qr, *kr, *vt, *sc, *at;
    cudaGetSymbolAddress((void**)&qp, g_q);
    cudaGetSymbolAddress((void**)&kp, g_k);
    cudaGetSymbolAddress((void**)&vp, g_v);
    cudaGetSymbolAddress((void**)&qr, g_qr);
    cudaGetSymbolAddress((void**)&kr, g_kr);
    cudaGetSymbolAddress((void**)&vt, g_vt);
    cudaGetSymbolAddress((void**)&sc, g_scores);
    cudaGetSymbolAddress((void**)&at, g_attn);

    const long long NOB = 1;  // no-batch zdiv
    // --- projections: [4096,1024] = X[4096,1024] @ W^T + b ---
    {
        dim3 grid(Ee / 128, BT / 128, 1);
        gemm_nt<128, 128, 16, 8, 8><<<grid, 256>>>(query, Wq, bq, qp,
            BT, Ee, Ee, Ee, Ee, Ee, 0, 0, 0, 0, (int)NOB);
        gemm_nt<128, 128, 16, 8, 8><<<grid, 256>>>(key, Wk, bk, kp,
            BT, Ee, Ee, Ee, Ee, Ee, 0, 0, 0, 0, (int)NOB);
        gemm_nt<128, 128, 16, 8, 8><<<grid, 256>>>(value, Wv, bv, vp,
            BT, Ee, Ee, Ee, Ee, Ee, 0, 0, 0, 0, (int)NOB);
    }

    // --- prune + split heads + xPos ---
    prune_transform<<<BT, 1024>>>(vp, vt, 0);
    prune_transform<<<BT, 1024>>>(qp, qr, 1);
    prune_transform<<<BT, 1024>>>(kp, kr, 2);

    // --- scores: per bh, S[2048,2048] = q_r @ k_r^T ---
    {
        dim3 grid(Tt / 128, Tt / 128, BH);
        gemm_nt<128, 128, 16, 8, 8><<<grid, 256>>>(qr, kr, nullptr, sc,
            Tt, Tt, Dd, Dd, Dd, Tt,
            (long long)Tt * Dd, (long long)Tt * Dd,
            0, (long long)Tt * Tt, 1 << 30);
    }

    // --- softmax + fp16 quantize; writes weights region of d_out ---
    {
        dim3 grid(Tt, BH);
        softmax_rows<<<grid, 256>>>(sc, out + OUT_OFF);
    }

    // --- PV: per bh, attn[2048,64] = probs @ v ; written straight into [B,T,E] layout ---
    {
        dim3 grid(Dd / 64, Tt / 64, BH);
        gemm_nt<64, 64, 16, 4, 4><<<grid, 256>>>(sc, vt, nullptr, at,
            Tt, Dd, Tt, Tt, Tt, Ee,
            (long long)Tt * Tt, (long long)Dd * Tt,
            (long long)Tt * Ee,     // per-b stride (z/16)
            (long long)Dd,          // per-h stride (z%16)
            16);
    }

    // --- output projection: out = attn @ Wo^T + bo ---
    {
        dim3 grid(Ee / 128, BT / 128, 1);
        gemm_nt<128, 128, 16, 8, 8><<<grid, 256>>>(at, Wo, bo, out,
            BT, Ee, Ee, Ee, Ee, Ee, 0, 0, 0, 0, (int)NOB);
    }
}

// round 10
// speedup vs baseline: 1.9570x; 1.9570x over previous
#include <cuda_runtime.h>
#include <cuda_fp16.h>
#include <cuda_bf16.h>
#include <math.h>
#include <stdint.h>

#define Bb 2
#define Tt 2048
#define Ee 1024
#define Dd 64
#define BH 32
#define BT 4096  // B*T

static const size_t OUT_OFF = (size_t)Bb * Tt * Ee;  // floats of `out`, then weights

// ---------------- scratch (device globals; no allocation allowed) ----------------
__device__ float g_q[BT * Ee];
__device__ float g_k[BT * Ee];
__device__ float g_v[BT * Ee];
__device__ float g_scores[(size_t)BH * Tt * Tt];   // fp32 scores
__device__ float g_attn[BT * Ee];

__device__ __nv_bfloat16 g_ahi[BT * Ee];           // activation split (reused)
__device__ __nv_bfloat16 g_alo[BT * Ee];
__device__ __nv_bfloat16 g_whi[Ee * Ee];           // weight split (reused)
__device__ __nv_bfloat16 g_wlo[Ee * Ee];
__device__ __nv_bfloat16 g_qrhi[BH * Tt * Dd];
__device__ __nv_bfloat16 g_qrlo[BH * Tt * Dd];
__device__ __nv_bfloat16 g_krhi[BH * Tt * Dd];
__device__ __nv_bfloat16 g_krlo[BH * Tt * Dd];
__device__ __nv_bfloat16 g_vthi[BH * Dd * Tt];     // [bh, d, t]
__device__ __nv_bfloat16 g_vtlo[BH * Dd * Tt];
__device__ __half g_p16[(size_t)BH * Tt * Tt];     // fp16 probs (exact)

// ================= low-level helpers (sm_80-class ISA only) =================
__device__ __forceinline__ uint32_t smem_u32(const void* p) {
    uint32_t a;
    asm("{ .reg .u64 t; cvta.to.shared.u64 t, %1; cvt.u32.u64 %0, t; }" : "=r"(a) : "l"(p));
    return a;
}
__device__ __forceinline__ void cpa16(uint32_t s, const void* g) {
    asm volatile("cp.async.ca.shared.global [%0], [%1], 16;" :: "r"(s), "l"(g));
}
#define CP_COMMIT() asm volatile("cp.async.commit_group;" ::: "memory")
#define CP_WAIT0()  asm volatile("cp.async.wait_group 0;" ::: "memory")
#define CP_WAIT1()  asm volatile("cp.async.wait_group 1;" ::: "memory")

__device__ __forceinline__ void ldsm4(uint32_t* r, uint32_t a) {
    asm volatile("ldmatrix.sync.aligned.m8n8.x4.shared.b16 {%0,%1,%2,%3}, [%4];"
                 : "=r"(r[0]), "=r"(r[1]), "=r"(r[2]), "=r"(r[3]) : "r"(a));
}
__device__ __forceinline__ void mma_bf16(float* d, const uint32_t* a, const uint32_t* b) {
    asm volatile("mma.sync.aligned.m16n8k16.row.col.f32.bf16.bf16.f32 "
                 "{%0,%1,%2,%3}, {%4,%5,%6,%7}, {%8,%9}, {%0,%1,%2,%3};"
                 : "+f"(d[0]), "+f"(d[1]), "+f"(d[2]), "+f"(d[3])
                 : "r"(a[0]), "r"(a[1]), "r"(a[2]), "r"(a[3]), "r"(b[0]), "r"(b[1]));
}
__device__ __forceinline__ uint32_t sw128(uint32_t off) { return off ^ ((off >> 3) & 0x70); }

// ================= bf16x3 NT GEMM on mma.sync =================
// C[M,N] = (Ahi+Alo)[M,K] * (Bhi+Blo)^T[N,K] (+bias), fp32 out.
// AMODE 0: A given as bf16 hi/lo global arrays (cp.async).
// AMODE 1: A given as fp16 global array; split to bf16 hi/lo during smem store (exact).
// BM=128, BK=64 (one 128B SW128 row per tile-row), 256 threads = 8 warps (4x2).
template <int BN, int AMODE>
__global__ void __launch_bounds__(256)
mma_gemm(const __nv_bfloat16* __restrict__ Ahi, const __nv_bfloat16* __restrict__ Alo,
         const __half* __restrict__ A16,
         const __nv_bfloat16* __restrict__ Bhi, const __nv_bfloat16* __restrict__ Blo,
         const float* __restrict__ bias, float* __restrict__ C,
         int M, int N, int K, int lda, int ldb, int ldc,
         long long sAz, long long sBz, long long sCz1, long long sCz2, int zdiv)
{
    constexpr int WN = BN / 2;          // warp cols
    constexpr int NT = WN / 8;          // n-tiles per warp
    constexpr int A_HI = 0;
    constexpr int A_LO = 16384;
    constexpr int B_HI = 32768;
    constexpr int B_LO = 32768 + BN * 128;
    constexpr int STAGE = 32768 + BN * 256;

    int z = blockIdx.z;
    if (AMODE == 0) { Ahi += (long long)z * sAz; Alo += (long long)z * sAz; }
    else            { A16 += (long long)z * sAz; }
    Bhi += (long long)z * sBz;  Blo += (long long)z * sBz;
    C   += (long long)(z / zdiv) * sCz1 + (long long)(z % zdiv) * sCz2;

    extern __shared__ char smem[];
    uint32_t smemU = smem_u32(smem);

    int tid = threadIdx.x;
    int wid = tid >> 5, lid = tid & 31;
    int row0 = blockIdx.y * 128;
    int col0 = blockIdx.x * BN;
    int wm0 = (wid & 3) * 32;
    int wn0 = (wid >> 2) * WN;

    float acc[2][NT][4];
#pragma unroll
    for (int mt = 0; mt < 2; mt++)
#pragma unroll
        for (int nt = 0; nt < NT; nt++)
#pragma unroll
            for (int j = 0; j < 4; j++) acc[mt][nt][j] = 0.0f;

    int NC = K >> 6;

    auto load_chunk = [&](int ch, int buf) {
        uint32_t s0 = smemU + buf * STAGE;
        char* sc = smem + buf * STAGE;
        int k0 = ch << 6;
        // ---- A tile: 128 rows x 64 bf16 (128B), hi+lo ----
        if (AMODE == 0) {
#pragma unroll
            for (int i = 0; i < 4; i++) {
                int u = tid + i * 256;          // 1024 16B units
                int r = u >> 3, ce = (u & 7) << 3;
                uint32_t sw = sw128((uint32_t)u << 4);
                size_t g = (size_t)(row0 + r) * lda + k0 + ce;
                cpa16(s0 + A_HI + sw, Ahi + g);
                cpa16(s0 + A_LO + sw, Alo + g);
            }
        } else {
#pragma unroll
            for (int i = 0; i < 4; i++) {
                int u = tid + i * 256;
                int r = u >> 3, ce = (u & 7) << 3;
                const __half2* gp = reinterpret_cast<const __half2*>(
                    A16 + (size_t)(row0 + r) * lda + k0 + ce);
                uint32_t hiw[4], low[4];
#pragma unroll
                for (int j = 0; j < 4; j++) {
                    float2 f = __half22float2(gp[j]);
                    __nv_bfloat16 h0 = __float2bfloat16(f.x);
                    __nv_bfloat16 h1 = __float2bfloat16(f.y);
                    __nv_bfloat16 l0 = __float2bfloat16(f.x - __bfloat162float(h0));
                    __nv_bfloat16 l1 = __float2bfloat16(f.y - __bfloat162float(h1));
                    __nv_bfloat162 hv = __halves2bfloat162(h0, h1);
                    __nv_bfloat162 lv = __halves2bfloat162(l0, l1);
                    hiw[j] = reinterpret_cast<uint32_t&>(hv);
                    low[j] = reinterpret_cast<uint32_t&>(lv);
                }
                uint32_t sw = sw128((uint32_t)u << 4);
                *reinterpret_cast<uint4*>(sc + A_HI + sw) = make_uint4(hiw[0], hiw[1], hiw[2], hiw[3]);
                *reinterpret_cast<uint4*>(sc + A_LO + sw) = make_uint4(low[0], low[1], low[2], low[3]);
            }
        }
        // ---- B tile: BN rows x 64 bf16, hi+lo ----
#pragma unroll
        for (int i = 0; i < BN / 32; i++) {
            int u = tid + i * 256;
            int r = u >> 3, ce = (u & 7) << 3;
            uint32_t sw = sw128((uint32_t)u << 4);
            size_t g = (size_t)(col0 + r) * ldb + k0 + ce;
            cpa16(s0 + B_HI + sw, Bhi + g);
            cpa16(s0 + B_LO + sw, Blo + g);
        }
    };

    // lane-constant ldmatrix addressing
    int aR = lid & 15;               // row within 16-row m-tile
    int aK = (lid >> 4) << 4;        // 0 / 16 bytes (k0-7 / k8-15)
    int bR = (lid & 7) + ((lid >> 4) << 3);   // row within 16-row n-pair
    int bK = ((lid >> 3) & 1) << 4;

    load_chunk(0, 0);
    CP_COMMIT();

    for (int ch = 0; ch < NC; ch++) {
        if (ch + 1 < NC) {
            load_chunk(ch + 1, (ch + 1) & 1);
            CP_COMMIT();
            CP_WAIT1();
        } else {
            CP_WAIT0();
        }
        __syncthreads();

        uint32_t sbase = smemU + (ch & 1) * STAGE;
#pragma unroll
        for (int ks = 0; ks < 4; ks++) {
            uint32_t ah[2][4], al[2][4];
#pragma unroll
            for (int mt = 0; mt < 2; mt++) {
                uint32_t off = (uint32_t)(wm0 + mt * 16 + aR) * 128 + (ks << 5) + aK;
                uint32_t sw = sw128(off);
                ldsm4(ah[mt], sbase + A_HI + sw);
                ldsm4(al[mt], sbase + A_LO + sw);
            }
#pragma unroll
            for (int np = 0; np < NT / 2; np++) {
                uint32_t off = (uint32_t)(wn0 + np * 16 + bR) * 128 + (ks << 5) + bK;
                uint32_t sw = sw128(off);
                uint32_t bh[4], bl[4];
                ldsm4(bh, sbase + B_HI + sw);
                ldsm4(bl, sbase + B_LO + sw);
#pragma unroll
                for (int mt = 0; mt < 2; mt++) {
                    mma_bf16(acc[mt][2 * np],     ah[mt], bh);
                    mma_bf16(acc[mt][2 * np],     ah[mt], bl);
                    mma_bf16(acc[mt][2 * np],     al[mt], bh);
                    mma_bf16(acc[mt][2 * np + 1], ah[mt], bh + 2);
                    mma_bf16(acc[mt][2 * np + 1], ah[mt], bl + 2);
                    mma_bf16(acc[mt][2 * np + 1], al[mt], bh + 2);
                }
            }
        }
        __syncthreads();
    }

    // ---- epilogue: registers -> global (float2 stores) ----
    int g = lid >> 2, tig = lid & 3;
#pragma unroll
    for (int mt = 0; mt < 2; mt++) {
#pragma unroll
        for (int nt = 0; nt < NT; nt++) {
            int r = row0 + wm0 + mt * 16 + g;
            int c = col0 + wn0 + nt * 8 + 2 * tig;
            float bx = 0.0f, by = 0.0f;
            if (bias) { bx = bias[c]; by = bias[c + 1]; }
            float2 v0 = make_float2(acc[mt][nt][0] + bx, acc[mt][nt][1] + by);
            float2 v1 = make_float2(acc[mt][nt][2] + bx, acc[mt][nt][3] + by);
            *reinterpret_cast<float2*>(&C[(size_t)r * ldc + c]) = v0;
            *reinterpret_cast<float2*>(&C[(size_t)(r + 8) * ldc + c]) = v1;
        }
    }
}

// ================= fp32 -> bf16 hi/lo split =================
__global__ void __launch_bounds__(256)
split_f32(const float* __restrict__ x, __nv_bfloat16* __restrict__ hi,
          __nv_bfloat16* __restrict__ lo, int n)
{
    int i = blockIdx.x * blockDim.x + threadIdx.x;
    if (i >= n) return;
    float v = x[i];
    __nv_bfloat16 h = __float2bfloat16(v);
    hi[i] = h;
    lo[i] = __float2bfloat16(v - __bfloat162float(h));
}

// ================= prune (top-512 of 1024) + head split + xPos, bf16 hi/lo out =================
__global__ void __launch_bounds__(1024)
prune_transform(const float* __restrict__ X, __nv_bfloat16* __restrict__ OH,
                __nv_bfloat16* __restrict__ OL, int mode)
{
    int row = blockIdx.x;
    int b = row >> 11;
    int t = row & 2047;
    int e = threadIdx.x;

    __shared__ float s[1024];
    __shared__ float vals[1024];

    float x = X[(size_t)row * 1024 + e];
    s[e] = x;
    __syncthreads();

    for (int k = 2; k <= 1024; k <<= 1) {
        for (int j = k >> 1; j > 0; j >>= 1) {
            int ixj = e ^ j;
            if (ixj > e) {
                float a = s[e], c = s[ixj];
                bool up = ((e & k) == 0);
                if ((a > c) == up) { s[e] = c; s[ixj] = a; }
            }
            __syncthreads();
        }
    }
    float thr = s[512];
    float m = (x >= thr) ? x : 0.0f;

    int h = e >> 6, d = e & 63;
    if (mode == 0) {
        size_t idx = ((size_t)(b * 16 + h) * 64 + d) * 2048 + t;
        __nv_bfloat16 mh = __float2bfloat16(m);
        OH[idx] = mh;
        OL[idx] = __float2bfloat16(m - __bfloat162float(mh));
        return;
    }
    if (mode == 1) m *= 0.125f;
    vals[e] = m;
    __syncthreads();

    int i = d >> 1;
    float base = (2.0f * (float)i + 25.6f) / 89.6f;
    float p = ((float)t - 1024.0f) / 512.0f;
    if (mode == 2) p = -p;
    float sc = powf(base, p);
    float freq = powf(10000.0f, -(float)i / 32.0f);
    float ang = (float)t * freq;
    float sn = sinf(ang) * sc;
    float cs = cosf(ang) * sc;
    float partner = vals[e ^ 1];
    float o = (d & 1) ? (m * cs + partner * sn) : (m * cs - partner * sn);
    size_t idx = ((size_t)(b * 16 + h) * 2048 + t) * 64 + d;
    __nv_bfloat16 oh = __float2bfloat16(o);
    OH[idx] = oh;
    OL[idx] = __float2bfloat16(o - __bfloat162float(oh));
}

// ================= softmax + fp16 quantize; emits fp32 weights + fp16 probs =================
__global__ void __launch_bounds__(256)
softmax_rows(const float* __restrict__ scores, float* __restrict__ wout,
             __half* __restrict__ P16)
{
    int t = blockIdx.x;
    int bh = blockIdx.y;
    const float* row = scores + ((size_t)bh * 2048 + t) * 2048;
    int tid = threadIdx.x;

    float v[8];
    float mx = -INFINITY;
#pragma unroll
    for (int i = 0; i < 8; i++) {
        v[i] = row[tid + i * 256];
        mx = fmaxf(mx, v[i]);
    }
    __shared__ float red[256];
    red[tid] = mx; __syncthreads();
    for (int s2 = 128; s2 > 0; s2 >>= 1) {
        if (tid < s2) red[tid] = fmaxf(red[tid], red[tid + s2]);
        __syncthreads();
    }
    mx = red[0];
    __syncthreads();

    float sm = 0.0f;
#pragma unroll
    for (int i = 0; i < 8; i++) { v[i] = expf(v[i] - mx); sm += v[i]; }
    red[tid] = sm; __syncthreads();
    for (int s2 = 128; s2 > 0; s2 >>= 1) {
        if (tid < s2) red[tid] += red[tid + s2];
        __syncthreads();
    }
    float inv = 1.0f / red[0];

    int b = bh >> 4, h = bh & 15;
    float* wrow = wout + ((size_t)(h * 2 + b) * 2048 + t) * 2048;
    size_t pbase = ((size_t)bh * 2048 + t) * 2048;
#pragma unroll
    for (int i = 0; i < 8; i++) {
        int c = tid + i * 256;
        __half hh = __float2half(v[i] * inv);   // fp32->fp16 RN (matches .astype(float16))
        wrow[c] = __half2float(hh);
        P16[pbase + c] = hh;
    }
}

// ================= host =================
extern "C" void kernel_launch(void* const* d_in, const int* in_sizes, int n_in,
                              void* d_out, int out_size)
{
    const float* query = (const float*)d_in[0];
    const float* key   = (const float*)d_in[1];
    const float* value = (const float*)d_in[2];
    const float* Wq = (const float*)d_in[3];
    const float* bq = (const float*)d_in[4];
    const float* Wk = (const float*)d_in[5];
    const float* bk = (const float*)d_in[6];
    const float* Wv = (const float*)d_in[7];
    const float* bv = (const float*)d_in[8];
    const float* Wo = (const float*)d_in[9];
    const float* bo = (const float*)d_in[10];
    float* out = (float*)d_out;

    float *qp, *kp, *vp, *sc, *at;
    __nv_bfloat16 *ahi, *alo, *whi, *wlo, *qrh, *qrl, *krh, *krl, *vth, *vtl;
    __half* p16;
    cudaGetSymbolAddress((void**)&qp, g_q);
    cudaGetSymbolAddress((void**)&kp, g_k);
    cudaGetSymbolAddress((void**)&vp, g_v);
    cudaGetSymbolAddress((void**)&sc, g_scores);
    cudaGetSymbolAddress((void**)&at, g_attn);
    cudaGetSymbolAddress((void**)&ahi, g_ahi);
    cudaGetSymbolAddress((void**)&alo, g_alo);
    cudaGetSymbolAddress((void**)&whi, g_whi);
    cudaGetSymbolAddress((void**)&wlo, g_wlo);
    cudaGetSymbolAddress((void**)&qrh, g_qrhi);
    cudaGetSymbolAddress((void**)&qrl, g_qrlo);
    cudaGetSymbolAddress((void**)&krh, g_krhi);
    cudaGetSymbolAddress((void**)&krl, g_krlo);
    cudaGetSymbolAddress((void**)&vth, g_vthi);
    cudaGetSymbolAddress((void**)&vtl, g_vtlo);
    cudaGetSymbolAddress((void**)&p16, g_p16);

    const int SM128 = 2 * (32768 + 128 * 256);   // 128 KB
    const int SM64  = 2 * (32768 + 64 * 256);    // 96 KB
    cudaFuncSetAttribute(mma_gemm<128, 0>, cudaFuncAttributeMaxDynamicSharedMemorySize, SM128);
    cudaFuncSetAttribute(mma_gemm<64, 1>,  cudaFuncAttributeMaxDynamicSharedMemorySize, SM64);

    const int NE = BT * Ee;
    const int NW = Ee * Ee;

    // --- projections (bf16x3 HMMA, fp32 out) ---
    struct { const float *x, *W, *b; float* C; } proj[3] = {
        {query, Wq, bq, qp}, {key, Wk, bk, kp}, {value, Wv, bv, vp}
    };
    for (int p = 0; p < 3; p++) {
        split_f32<<<(NE + 255) / 256, 256>>>(proj[p].x, ahi, alo, NE);
        split_f32<<<(NW + 255) / 256, 256>>>(proj[p].W, whi, wlo, NW);
        dim3 grid(Ee / 128, BT / 128, 1);
        mma_gemm<128, 0><<<grid, 256, SM128>>>(
            ahi, alo, nullptr, whi, wlo, proj[p].b, proj[p].C,
            BT, Ee, Ee, Ee, Ee, Ee, 0, 0, 0, 0, 1);
    }

    // --- prune + split heads + xPos (emit bf16 hi/lo) ---
    prune_transform<<<BT, 1024>>>(vp, vth, vtl, 0);
    prune_transform<<<BT, 1024>>>(qp, qrh, qrl, 1);
    prune_transform<<<BT, 1024>>>(kp, krh, krl, 2);

    // --- scores: per bh, S[2048,2048] = q @ k^T, K=64 ---
    {
        dim3 grid(Tt / 128, Tt / 128, BH);
        mma_gemm<128, 0><<<grid, 256, SM128>>>(
            qrh, qrl, nullptr, krh, krl, nullptr, sc,
            Tt, Tt, Dd, Dd, Dd, Tt,
            (long long)Tt * Dd, (long long)Tt * Dd,
            (long long)Tt * Tt, 0, 1);
    }

    // --- softmax + fp16 quantize; weights region of d_out + fp16 probs ---
    {
        dim3 grid(Tt, BH);
        softmax_rows<<<grid, 256>>>(sc, out + OUT_OFF, p16);
    }

    // --- PV: per bh, attn[2048,64] = probs(fp16, split on the fly) @ v ---
    {
        dim3 grid(1, Tt / 128, BH);
        mma_gemm<64, 1><<<grid, 256, SM64>>>(
            nullptr, nullptr, p16, vth, vtl, nullptr, at,
            Tt, Dd, Tt, Tt, Tt, Ee,
            (long long)Tt * Tt, (long long)Dd * Tt,
            (long long)Tt * Ee,     // per-b stride (z/16)
            (long long)Dd,          // per-h stride (z%16)
            16);
    }

    // --- output projection ---
    {
        split_f32<<<(NE + 255) / 256, 256>>>(at, ahi, alo, NE);
        split_f32<<<(NW + 255) / 256, 256>>>(Wo, whi, wlo, NW);
        dim3 grid(Ee / 128, BT / 128, 1);
        mma_gemm<128, 0><<<grid, 256, SM128>>>(
            ahi, alo, nullptr, whi, wlo, bo, out,
            BT, Ee, Ee, Ee, Ee, Ee, 0, 0, 0, 0, 1);
    }
}

// round 11
// speedup vs baseline: 2.4175x; 1.2353x over previous
#include <cuda_runtime.h>
#include <cuda_fp16.h>
#include <cuda_bf16.h>
#include <math.h>
#include <stdint.h>

#define Bb 2
#define Tt 2048
#define Ee 1024
#define Dd 64
#define BH 32
#define BT 4096  // B*T

static const size_t OUT_OFF = (size_t)Bb * Tt * Ee;  // floats of `out`, then weights

// ---------------- scratch (device globals; no allocation allowed) ----------------
__device__ float g_q[BT * Ee];
__device__ float g_k[BT * Ee];
__device__ float g_v[BT * Ee];
__device__ float g_scores[(size_t)BH * Tt * Tt];   // fp32 scores
__device__ float g_attn[BT * Ee];

__device__ __nv_bfloat16 g_ahi[BT * Ee];           // activation split (reused)
__device__ __nv_bfloat16 g_alo[BT * Ee];
__device__ __nv_bfloat16 g_whi[Ee * Ee];           // weight split (reused)
__device__ __nv_bfloat16 g_wlo[Ee * Ee];
__device__ __nv_bfloat16 g_qrhi[BH * Tt * Dd];
__device__ __nv_bfloat16 g_qrlo[BH * Tt * Dd];
__device__ __nv_bfloat16 g_krhi[BH * Tt * Dd];
__device__ __nv_bfloat16 g_krlo[BH * Tt * Dd];
__device__ __nv_bfloat16 g_vthi[BH * Dd * Tt];     // [bh, d, t]
__device__ __nv_bfloat16 g_vtlo[BH * Dd * Tt];

// ================= low-level helpers (sm_80-class ISA only) =================
__device__ __forceinline__ uint32_t smem_u32(const void* p) {
    uint32_t a;
    asm("{ .reg .u64 t; cvta.to.shared.u64 t, %1; cvt.u32.u64 %0, t; }" : "=r"(a) : "l"(p));
    return a;
}
__device__ __forceinline__ void cpa16(uint32_t s, const void* g) {
    asm volatile("cp.async.ca.shared.global [%0], [%1], 16;" :: "r"(s), "l"(g));
}
#define CP_COMMIT() asm volatile("cp.async.commit_group;" ::: "memory")
#define CP_WAIT0()  asm volatile("cp.async.wait_group 0;" ::: "memory")
#define CP_WAIT1()  asm volatile("cp.async.wait_group 1;" ::: "memory")

__device__ __forceinline__ void ldsm4(uint32_t* r, uint32_t a) {
    asm volatile("ldmatrix.sync.aligned.m8n8.x4.shared.b16 {%0,%1,%2,%3}, [%4];"
                 : "=r"(r[0]), "=r"(r[1]), "=r"(r[2]), "=r"(r[3]) : "r"(a));
}
__device__ __forceinline__ void mma_bf16(float* d, const uint32_t* a, const uint32_t* b) {
    asm volatile("mma.sync.aligned.m16n8k16.row.col.f32.bf16.bf16.f32 "
                 "{%0,%1,%2,%3}, {%4,%5,%6,%7}, {%8,%9}, {%0,%1,%2,%3};"
                 : "+f"(d[0]), "+f"(d[1]), "+f"(d[2]), "+f"(d[3])
                 : "r"(a[0]), "r"(a[1]), "r"(a[2]), "r"(a[3]), "r"(b[0]), "r"(b[1]));
}
__device__ __forceinline__ uint32_t sw128(uint32_t off) { return off ^ ((off >> 3) & 0x70); }

__device__ __forceinline__ void split8_pack(const float* f, uint32_t* hiw, uint32_t* low) {
#pragma unroll
    for (int j = 0; j < 4; j++) {
        float f0 = f[2 * j], f1 = f[2 * j + 1];
        __nv_bfloat16 h0 = __float2bfloat16(f0);
        __nv_bfloat16 h1 = __float2bfloat16(f1);
        __nv_bfloat16 l0 = __float2bfloat16(f0 - __bfloat162float(h0));
        __nv_bfloat16 l1 = __float2bfloat16(f1 - __bfloat162float(h1));
        __nv_bfloat162 hv = __halves2bfloat162(h0, h1);
        __nv_bfloat162 lv = __halves2bfloat162(l0, l1);
        hiw[j] = reinterpret_cast<uint32_t&>(hv);
        low[j] = reinterpret_cast<uint32_t&>(lv);
    }
}

// ================= bf16x3 NT GEMM on mma.sync =================
// C[M,N] = (Ahi+Alo)[M,K] * (Bhi+Blo)^T[N,K] (+bias), fp32 out.
// AMODE 0: A given as bf16 hi/lo global arrays (cp.async).
// AMODE 2: A given as fp32 global array (attn weights layout, z -> (z&15)*2+(z>>4));
//          split to bf16 hi/lo during smem store (exact for fp16-valued data).
// BM=128, BK=64, 256 threads = 8 warps (4x2).
template <int BN, int AMODE>
__global__ void __launch_bounds__(256)
mma_gemm(const __nv_bfloat16* __restrict__ Ahi, const __nv_bfloat16* __restrict__ Alo,
         const float* __restrict__ A32,
         const __nv_bfloat16* __restrict__ Bhi, const __nv_bfloat16* __restrict__ Blo,
         const float* __restrict__ bias, float* __restrict__ C,
         int M, int N, int K, int lda, int ldb, int ldc,
         long long sAz, long long sBz, long long sCz1, long long sCz2, int zdiv)
{
    constexpr int WN = BN / 2;          // warp cols
    constexpr int NT = WN / 8;          // n-tiles per warp
    constexpr int A_HI = 0;
    constexpr int A_LO = 16384;
    constexpr int B_HI = 32768;
    constexpr int B_LO = 32768 + BN * 128;
    constexpr int STAGE = 32768 + BN * 256;

    int z = blockIdx.z;
    if (AMODE == 0) { Ahi += (long long)z * sAz; Alo += (long long)z * sAz; }
    else { int zm = (z & 15) * 2 + (z >> 4); A32 += (long long)zm * sAz; }
    Bhi += (long long)z * sBz;  Blo += (long long)z * sBz;
    C   += (long long)(z / zdiv) * sCz1 + (long long)(z % zdiv) * sCz2;

    extern __shared__ char smem[];
    uint32_t smemU = smem_u32(smem);

    int tid = threadIdx.x;
    int wid = tid >> 5, lid = tid & 31;
    int row0 = blockIdx.y * 128;
    int col0 = blockIdx.x * BN;
    int wm0 = (wid & 3) * 32;
    int wn0 = (wid >> 2) * WN;

    float acc[2][NT][4];
#pragma unroll
    for (int mt = 0; mt < 2; mt++)
#pragma unroll
        for (int nt = 0; nt < NT; nt++)
#pragma unroll
            for (int j = 0; j < 4; j++) acc[mt][nt][j] = 0.0f;

    int NC = K >> 6;

    auto load_chunk = [&](int ch, int buf) {
        uint32_t s0 = smemU + buf * STAGE;
        char* scm = smem + buf * STAGE;
        int k0 = ch << 6;
        if (AMODE == 0) {
#pragma unroll
            for (int i = 0; i < 4; i++) {
                int u = tid + i * 256;          // 1024 16B units
                int r = u >> 3, ce = (u & 7) << 3;
                uint32_t sw = sw128((uint32_t)u << 4);
                size_t g = (size_t)(row0 + r) * lda + k0 + ce;
                cpa16(s0 + A_HI + sw, Ahi + g);
                cpa16(s0 + A_LO + sw, Alo + g);
            }
        } else {
#pragma unroll
            for (int i = 0; i < 4; i++) {
                int u = tid + i * 256;
                int r = u >> 3, ce = (u & 7) << 3;
                const float* gp = A32 + (size_t)(row0 + r) * lda + k0 + ce;
                float f[8];
                *reinterpret_cast<float4*>(f)     = *reinterpret_cast<const float4*>(gp);
                *reinterpret_cast<float4*>(f + 4) = *reinterpret_cast<const float4*>(gp + 4);
                uint32_t hiw[4], low[4];
                split8_pack(f, hiw, low);
                uint32_t sw = sw128((uint32_t)u << 4);
                *reinterpret_cast<uint4*>(scm + A_HI + sw) = make_uint4(hiw[0], hiw[1], hiw[2], hiw[3]);
                *reinterpret_cast<uint4*>(scm + A_LO + sw) = make_uint4(low[0], low[1], low[2], low[3]);
            }
        }
#pragma unroll
        for (int i = 0; i < BN / 32; i++) {
            int u = tid + i * 256;
            int r = u >> 3, ce = (u & 7) << 3;
            uint32_t sw = sw128((uint32_t)u << 4);
            size_t g = (size_t)(col0 + r) * ldb + k0 + ce;
            cpa16(s0 + B_HI + sw, Bhi + g);
            cpa16(s0 + B_LO + sw, Blo + g);
        }
    };

    int aR = lid & 15;
    int aK = (lid >> 4) << 4;
    int bR = (lid & 7) + ((lid >> 4) << 3);
    int bK = ((lid >> 3) & 1) << 4;

    load_chunk(0, 0);
    CP_COMMIT();

    for (int ch = 0; ch < NC; ch++) {
        if (ch + 1 < NC) {
            load_chunk(ch + 1, (ch + 1) & 1);
            CP_COMMIT();
            CP_WAIT1();
        } else {
            CP_WAIT0();
        }
        __syncthreads();

        uint32_t sbase = smemU + (ch & 1) * STAGE;
#pragma unroll
        for (int ks = 0; ks < 4; ks++) {
            uint32_t ah[2][4], al[2][4];
#pragma unroll
            for (int mt = 0; mt < 2; mt++) {
                uint32_t off = (uint32_t)(wm0 + mt * 16 + aR) * 128 + (ks << 5) + aK;
                uint32_t sw = sw128(off);
                ldsm4(ah[mt], sbase + A_HI + sw);
                ldsm4(al[mt], sbase + A_LO + sw);
            }
#pragma unroll
            for (int np = 0; np < NT / 2; np++) {
                uint32_t off = (uint32_t)(wn0 + np * 16 + bR) * 128 + (ks << 5) + bK;
                uint32_t sw = sw128(off);
                uint32_t bh[4], bl[4];
                ldsm4(bh, sbase + B_HI + sw);
                ldsm4(bl, sbase + B_LO + sw);
#pragma unroll
                for (int mt = 0; mt < 2; mt++) {
                    mma_bf16(acc[mt][2 * np],     ah[mt], bh);
                    mma_bf16(acc[mt][2 * np],     ah[mt], bl);
                    mma_bf16(acc[mt][2 * np],     al[mt], bh);
                    mma_bf16(acc[mt][2 * np + 1], ah[mt], bh + 2);
                    mma_bf16(acc[mt][2 * np + 1], ah[mt], bl + 2);
                    mma_bf16(acc[mt][2 * np + 1], al[mt], bh + 2);
                }
            }
        }
        __syncthreads();
    }

    int g = lid >> 2, tig = lid & 3;
#pragma unroll
    for (int mt = 0; mt < 2; mt++) {
#pragma unroll
        for (int nt = 0; nt < NT; nt++) {
            int r = row0 + wm0 + mt * 16 + g;
            int c = col0 + wn0 + nt * 8 + 2 * tig;
            float bx = 0.0f, by = 0.0f;
            if (bias) { bx = bias[c]; by = bias[c + 1]; }
            float2 v0 = make_float2(acc[mt][nt][0] + bx, acc[mt][nt][1] + by);
            float2 v1 = make_float2(acc[mt][nt][2] + bx, acc[mt][nt][3] + by);
            *reinterpret_cast<float2*>(&C[(size_t)r * ldc + c]) = v0;
            *reinterpret_cast<float2*>(&C[(size_t)(r + 8) * ldc + c]) = v1;
        }
    }
}

// ================= fp32 -> bf16 hi/lo split (vectorized) =================
__global__ void __launch_bounds__(256)
split_f32(const float4* __restrict__ x, uint2* __restrict__ hi,
          uint2* __restrict__ lo, int n4)
{
    int i = blockIdx.x * blockDim.x + threadIdx.x;
    if (i >= n4) return;
    float4 v = x[i];
    __nv_bfloat16 h0 = __float2bfloat16(v.x), h1 = __float2bfloat16(v.y);
    __nv_bfloat16 h2 = __float2bfloat16(v.z), h3 = __float2bfloat16(v.w);
    __nv_bfloat16 l0 = __float2bfloat16(v.x - __bfloat162float(h0));
    __nv_bfloat16 l1 = __float2bfloat16(v.y - __bfloat162float(h1));
    __nv_bfloat16 l2 = __float2bfloat16(v.z - __bfloat162float(h2));
    __nv_bfloat16 l3 = __float2bfloat16(v.w - __bfloat162float(h3));
    __nv_bfloat162 ha = __halves2bfloat162(h0, h1), hb = __halves2bfloat162(h2, h3);
    __nv_bfloat162 la = __halves2bfloat162(l0, l1), lb = __halves2bfloat162(l2, l3);
    hi[i] = make_uint2(reinterpret_cast<uint32_t&>(ha), reinterpret_cast<uint32_t&>(hb));
    lo[i] = make_uint2(reinterpret_cast<uint32_t&>(la), reinterpret_cast<uint32_t&>(lb));
}

// ================= prune via radix select + head split + xPos, bf16 hi/lo out =================
// blockIdx.y: 0 = v -> [bh,d,t], 1 = q (scale+xPos up), 2 = k (xPos down) -> [bh,t,d]
__global__ void __launch_bounds__(1024)
prune_radix(const float* __restrict__ Xv, const float* __restrict__ Xq, const float* __restrict__ Xk,
            __nv_bfloat16* __restrict__ VH, __nv_bfloat16* __restrict__ VL,
            __nv_bfloat16* __restrict__ QH, __nv_bfloat16* __restrict__ QL,
            __nv_bfloat16* __restrict__ KH, __nv_bfloat16* __restrict__ KL)
{
    int mode = blockIdx.y;
    const float* X = (mode == 0) ? Xv : (mode == 1) ? Xq : Xk;
    __nv_bfloat16* OH = (mode == 0) ? VH : (mode == 1) ? QH : KH;
    __nv_bfloat16* OL = (mode == 0) ? VL : (mode == 1) ? QL : KL;

    int row = blockIdx.x;            // b*T + t
    int b = row >> 11;
    int t = row & 2047;
    int e = threadIdx.x;

    __shared__ uint32_t hist[256];
    __shared__ uint32_t s_bin;

    float x = X[(size_t)row * 1024 + e];
    uint32_t bits = __float_as_uint(x);
    uint32_t u = bits ^ ((uint32_t)((int)bits >> 31) | 0x80000000u);  // order-preserving key

    // 4-pass radix select for ascending rank 512 (the 512th-largest value)
    uint32_t prefix = 0;
    bool active = true;
    uint32_t tgt = 512;              // live in warp-0 registers
#pragma unroll
    for (int shift = 24; shift >= 0; shift -= 8) {
        if (e < 256) hist[e] = 0;
        __syncthreads();
        if (active) atomicAdd(&hist[(u >> shift) & 255], 1);
        __syncthreads();
        if (e < 32) {
            uint32_t cnt[8], lsum = 0;
#pragma unroll
            for (int j = 0; j < 8; j++) { cnt[j] = hist[e * 8 + j]; lsum += cnt[j]; }
            uint32_t inc = lsum;
#pragma unroll
            for (int o = 1; o < 32; o <<= 1) {
                uint32_t vv = __shfl_up_sync(0xffffffffu, inc, o);
                if (e >= o) inc += vv;
            }
            uint32_t exc = inc - lsum;
            bool has = (exc <= tgt) && (tgt < inc);
            uint32_t binv = 0, ntgt = 0;
            if (has) {
                uint32_t c = exc;
                bool done = false;
#pragma unroll
                for (int j = 0; j < 8; j++) {
                    uint32_t nc = c + cnt[j];
                    if (!done && tgt < nc) { binv = e * 8 + j; ntgt = tgt - c; done = true; }
                    c = nc;
                }
            }
            uint32_t bal = __ballot_sync(0xffffffffu, has);
            int src = __ffs(bal) - 1;
            binv = __shfl_sync(0xffffffffu, binv, src);
            tgt  = __shfl_sync(0xffffffffu, ntgt, src);
            if (e == 0) s_bin = binv;
        }
        __syncthreads();
        uint32_t bin = s_bin;
        prefix |= bin << shift;
        active = active && (((u >> shift) & 255) == bin);
        __syncthreads();
    }

    uint32_t tb = (prefix & 0x80000000u) ? (prefix ^ 0x80000000u) : ~prefix;
    float thr = __uint_as_float(tb);
    float m = (x >= thr) ? x : 0.0f;

    int h = e >> 6, d = e & 63;
    if (mode == 0) {
        size_t idx = ((size_t)(b * 16 + h) * 64 + d) * 2048 + t;
        __nv_bfloat16 mh = __float2bfloat16(m);
        OH[idx] = mh;
        OL[idx] = __float2bfloat16(m - __bfloat162float(mh));
        return;
    }
    if (mode == 1) m *= 0.125f;

    int i = d >> 1;
    float base = (2.0f * (float)i + 25.6f) / 89.6f;
    float p = ((float)t - 1024.0f) / 512.0f;
    if (mode == 2) p = -p;
    float scl = powf(base, p);
    float freq = powf(10000.0f, -(float)i / 32.0f);
    float ang = (float)t * freq;
    float sn = sinf(ang) * scl;
    float cs = cosf(ang) * scl;
    float partner = __shfl_xor_sync(0xffffffffu, m, 1);
    float o = (d & 1) ? (m * cs + partner * sn) : (m * cs - partner * sn);
    size_t idx = ((size_t)(b * 16 + h) * 2048 + t) * 64 + d;
    __nv_bfloat16 oh = __float2bfloat16(o);
    OH[idx] = oh;
    OL[idx] = __float2bfloat16(o - __bfloat162float(oh));
}

// ================= softmax + fp16 quantize; writes fp32 weights region of d_out =================
__global__ void __launch_bounds__(256)
softmax_rows(const float* __restrict__ scores, float* __restrict__ wout)
{
    int t = blockIdx.x;
    int bh = blockIdx.y;
    const float* row = scores + ((size_t)bh * 2048 + t) * 2048;
    int tid = threadIdx.x;
    int lane = tid & 31, warp = tid >> 5;
    __shared__ float red[8];

    float v[8];
    float mx = -INFINITY;
#pragma unroll
    for (int i = 0; i < 8; i++) {
        v[i] = row[tid + i * 256];
        mx = fmaxf(mx, v[i]);
    }
#pragma unroll
    for (int o = 16; o > 0; o >>= 1) mx = fmaxf(mx, __shfl_xor_sync(0xffffffffu, mx, o));
    if (lane == 0) red[warp] = mx;
    __syncthreads();
    mx = red[0];
#pragma unroll
    for (int w = 1; w < 8; w++) mx = fmaxf(mx, red[w]);
    __syncthreads();

    float sm = 0.0f;
#pragma unroll
    for (int i = 0; i < 8; i++) { v[i] = expf(v[i] - mx); sm += v[i]; }
#pragma unroll
    for (int o = 16; o > 0; o >>= 1) sm += __shfl_xor_sync(0xffffffffu, sm, o);
    if (lane == 0) red[warp] = sm;
    __syncthreads();
    sm = red[0];
#pragma unroll
    for (int w = 1; w < 8; w++) sm += red[w];
    float inv = 1.0f / sm;

    int b = bh >> 4, h = bh & 15;
    float* wrow = wout + ((size_t)(h * 2 + b) * 2048 + t) * 2048;
#pragma unroll
    for (int i = 0; i < 8; i++) {
        __half hh = __float2half(v[i] * inv);   // fp32->fp16 RN (matches .astype(float16))
        wrow[tid + i * 256] = __half2float(hh);
    }
}

// ================= host =================
extern "C" void kernel_launch(void* const* d_in, const int* in_sizes, int n_in,
                              void* d_out, int out_size)
{
    const float* query = (const float*)d_in[0];
    const float* key   = (const float*)d_in[1];
    const float* value = (const float*)d_in[2];
    const float* Wq = (const float*)d_in[3];
    const float* bq = (const float*)d_in[4];
    const float* Wk = (const float*)d_in[5];
    const float* bk = (const float*)d_in[6];
    const float* Wv = (const float*)d_in[7];
    const float* bv = (const float*)d_in[8];
    const float* Wo = (const float*)d_in[9];
    const float* bo = (const float*)d_in[10];
    float* out = (float*)d_out;

    float *qp, *kp, *vp, *sc, *at;
    __nv_bfloat16 *ahi, *alo, *whi, *wlo, *qrh, *qrl, *krh, *krl, *vth, *vtl;
    cudaGetSymbolAddress((void**)&qp, g_q);
    cudaGetSymbolAddress((void**)&kp, g_k);
    cudaGetSymbolAddress((void**)&vp, g_v);
    cudaGetSymbolAddress((void**)&sc, g_scores);
    cudaGetSymbolAddress((void**)&at, g_attn);
    cudaGetSymbolAddress((void**)&ahi, g_ahi);
    cudaGetSymbolAddress((void**)&alo, g_alo);
    cudaGetSymbolAddress((void**)&whi, g_whi);
    cudaGetSymbolAddress((void**)&wlo, g_wlo);
    cudaGetSymbolAddress((void**)&qrh, g_qrhi);
    cudaGetSymbolAddress((void**)&qrl, g_qrlo);
    cudaGetSymbolAddress((void**)&krh, g_krhi);
    cudaGetSymbolAddress((void**)&krl, g_krlo);
    cudaGetSymbolAddress((void**)&vth, g_vthi);
    cudaGetSymbolAddress((void**)&vtl, g_vtlo);

    const int SM128 = 2 * (32768 + 128 * 256);   // 128 KB
    const int SM64  = 2 * (32768 + 64 * 256);    // 96 KB
    cudaFuncSetAttribute(mma_gemm<128, 0>, cudaFuncAttributeMaxDynamicSharedMemorySize, SM128);
    cudaFuncSetAttribute(mma_gemm<64, 2>,  cudaFuncAttributeMaxDynamicSharedMemorySize, SM64);

    const int NE = BT * Ee;
    const int NW = Ee * Ee;

    // --- projections (bf16x3 HMMA, fp32 out) ---
    struct { const float *x, *W, *b; float* C; } proj[3] = {
        {query, Wq, bq, qp}, {key, Wk, bk, kp}, {value, Wv, bv, vp}
    };
    for (int p = 0; p < 3; p++) {
        split_f32<<<(NE / 4 + 255) / 256, 256>>>((const float4*)proj[p].x, (uint2*)ahi, (uint2*)alo, NE / 4);
        split_f32<<<(NW / 4 + 255) / 256, 256>>>((const float4*)proj[p].W, (uint2*)whi, (uint2*)wlo, NW / 4);
        dim3 grid(Ee / 128, BT / 128, 1);
        mma_gemm<128, 0><<<grid, 256, SM128>>>(
            ahi, alo, nullptr, whi, wlo, proj[p].b, proj[p].C,
            BT, Ee, Ee, Ee, Ee, Ee, 0, 0, 0, 0, 1);
    }

    // --- prune (radix select) + split heads + xPos, all three in one launch ---
    {
        dim3 grid(BT, 3);
        prune_radix<<<grid, 1024>>>(vp, qp, kp, vth, vtl, qrh, qrl, krh, krl);
    }

    // --- scores: per bh, S[2048,2048] = q @ k^T, K=64 ---
    {
        dim3 grid(Tt / 128, Tt / 128, BH);
        mma_gemm<128, 0><<<grid, 256, SM128>>>(
            qrh, qrl, nullptr, krh, krl, nullptr, sc,
            Tt, Tt, Dd, Dd, Dd, Tt,
            (long long)Tt * Dd, (long long)Tt * Dd,
            (long long)Tt * Tt, 0, 1);
    }

    // --- softmax + fp16 quantize -> weights region of d_out (fp32) ---
    {
        dim3 grid(Tt, BH);
        softmax_rows<<<grid, 256>>>(sc, out + OUT_OFF);
    }

    // --- PV: per bh, attn[2048,64] = weights(fp32, split on the fly) @ v ---
    {
        dim3 grid(1, Tt / 128, BH);
        mma_gemm<64, 2><<<grid, 256, SM64>>>(
            nullptr, nullptr, out + OUT_OFF, vth, vtl, nullptr, at,
            Tt, Dd, Tt, Tt, Tt, Ee,
            (long long)Tt * Tt, (long long)Dd * Tt,
            (long long)Tt * Ee,     // per-b stride (z/16)
            (long long)Dd,          // per-h stride (z%16)
            16);
    }

    // --- output projection ---
    {
        split_f32<<<(NE / 4 + 255) / 256, 256>>>((const float4*)at, (uint2*)ahi, (uint2*)alo, NE / 4);
        split_f32<<<(NW / 4 + 255) / 256, 256>>>((const float4*)Wo, (uint2*)whi, (uint2*)wlo, NW / 4);
        dim3 grid(Ee / 128, BT / 128, 1);
        mma_gemm<128, 0><<<grid, 256, SM128>>>(
            ahi, alo, nullptr, whi, wlo, bo, out,
            BT, Ee, Ee, Ee, Ee, Ee, 0, 0, 0, 0, 1);
    }
}